// round 14
// baseline (speedup 1.0000x reference)
#include <cuda_runtime.h>
#include <math.h>

#define B_  32
#define T0_ 2048
#define T1_ 2044
#define T2_ 2040
#define T3_ 2034

// ---------------- scratch (device globals; no allocations allowed) ----------
__device__ float g_xT  [20   * B_ * T0_];
__device__ float g_act1[512  * B_ * T1_];
__device__ float g_act2[512  * B_ * T2_];
__device__ float g_act3[512  * B_ * T3_];
__device__ float g_act4[512  * B_ * T3_];
__device__ float g_act5[1500 * B_ * T3_];
__device__ float g_scl [1500];
__device__ float g_shf [1500];
__device__ __align__(16) uint2 g_wp[512 * 1536 / 2];  // packed bf16 hi/lo pairs [K/2][M]
__device__ float g_bp  [1500];
__device__ float g_pool[B_ * 3000];
__device__ float g_y1  [B_ * 512];
__device__ float g_y2  [B_ * 512];

// ---------------- transpose x[b][t][f] -> xT[f][b][t] -----------------------
__global__ void transpose_x(const float* __restrict__ x, float* __restrict__ xT) {
    int idx = blockIdx.x * blockDim.x + threadIdx.x;
    const int total = B_ * T0_ * 20;
    if (idx >= total) return;
    int f = idx % 20;
    int t = (idx / 20) % T0_;
    int b = idx / (20 * T0_);
    xT[((size_t)f * B_ + b) * T0_ + t] = x[idx];
}

// ---------------- BF16 split helpers -----------------------------------------
__device__ __forceinline__ void pack_split_bf16(float v0, float v1,
                                                unsigned &hi, unsigned &lo) {
    unsigned h;
    asm("cvt.rn.bf16x2.f32 %0, %1, %2;" : "=r"(h) : "f"(v1), "f"(v0));
    float h0 = __uint_as_float(h << 16);
    float h1 = __uint_as_float(h & 0xffff0000u);
    float l0 = v0 - h0;
    float l1 = v1 - h1;
    unsigned l;
    asm("cvt.rn.bf16x2.f32 %0, %1, %2;" : "=r"(l) : "f"(l1), "f"(l0));
    hi = h; lo = l;
}

// ---------------- weight prep: transpose + fold BN scale + bf16 split --------
__global__ void prep_wp(const float* __restrict__ W, const float* __restrict__ scl,
                        uint2* __restrict__ Wp, int M, int K, int C, int hasAff)
{
    int idx = blockIdx.x * blockDim.x + threadIdx.x;
    int total = (K >> 1) * M;
    if (idx >= total) return;
    int kp = idx / M, m = idx - kp * M;
    int k0 = 2 * kp, k1 = 2 * kp + 1;
    float s0 = hasAff ? scl[k0 / C] : 1.f;
    float s1 = hasAff ? scl[k1 / C] : 1.f;
    float v0 = W[(size_t)m * K + k0] * s0;
    float v1 = W[(size_t)m * K + k1] * s1;
    unsigned h, l;
    pack_split_bf16(v0, v1, h, l);
    Wp[idx] = make_uint2(h, l);
}
__global__ void prep_bias(const float* __restrict__ W, const float* __restrict__ bias,
                          const float* __restrict__ shf, float* __restrict__ bp,
                          int M, int K, int C, int hasAff)
{
    int m    = blockIdx.x * (blockDim.x >> 5) + (threadIdx.x >> 5);
    int lane = threadIdx.x & 31;
    if (m >= M) return;
    float acc = 0.f;
    if (hasAff)
        for (int k = lane; k < K; k += 32) acc += W[(size_t)m * K + k] * shf[k / C];
#pragma unroll
    for (int off = 16; off; off >>= 1) acc += __shfl_xor_sync(0xffffffffu, acc, off);
    if (lane == 0) bp[m] = bias[m] + acc;
}

// ---------------- mma / cp.async helpers -------------------------------------
__device__ __forceinline__ void mma_bf16(float c[4],
                                         unsigned a0, unsigned a1, unsigned a2, unsigned a3,
                                         unsigned b0, unsigned b1) {
    asm("mma.sync.aligned.m16n8k16.row.col.f32.bf16.bf16.f32 "
        "{%0,%1,%2,%3}, {%4,%5,%6,%7}, {%8,%9}, {%0,%1,%2,%3};"
        : "+f"(c[0]), "+f"(c[1]), "+f"(c[2]), "+f"(c[3])
        : "r"(a0), "r"(a1), "r"(a2), "r"(a3), "r"(b0), "r"(b1));
}
__device__ __forceinline__ unsigned smem_u32(const void* p) {
    return (unsigned)__cvta_generic_to_shared(p);
}
__device__ __forceinline__ void cp16(unsigned dst, const void* src, int sbytes) {
    asm volatile("cp.async.ca.shared.global [%0], [%1], 16, %2;"
                 :: "r"(dst), "l"(src), "r"(sbytes));
}
__device__ __forceinline__ void cp4(unsigned dst, const float* src, int sbytes) {
    asm volatile("cp.async.ca.shared.global [%0], [%1], 4, %2;"
                 :: "r"(dst), "l"(src), "r"(sbytes));
}

// ---------------- fused splice + 1x1 conv GEMM -------------------------------
// 3xBF16 split-precision tensor-core GEMM (m16n8k16, fp32 accumulate).
// Block 128x128x32 (TBK=32, dynamic smem, 2 CTAs/SM), 8 warps, warp tile 64x32.
// A: pre-split packed bf16 hi/lo uint2 (prep_wp) via cp.async -> LDS.64 frags.
// B: raw fp32 via cp.async, split+packed at fragment load.
// MMA issued PASS-MAJOR: 16 independent mma between dependent accumulations.
#define TBM 128
#define TBN 128
#define TBK 32
#define KPA 16        // k-pair rows per tile (A)
#define PADA 4        // uint2 pad
#define PADB 4        // float pad
#define A_TILE_BYTES (2 * KPA * (TBM + PADA) * 8)       // 33792
#define B_TILE_BYTES (2 * TBK * (TBN + PADB) * 4)       // 33792
#define SMEM_TOTAL_G (A_TILE_BYTES + B_TILE_BYTES)      // 67584

__global__ __launch_bounds__(256, 2)
void gemm_splice(const uint2* __restrict__ Wp, const float* __restrict__ bias,
                 const float* __restrict__ X, float* __restrict__ Y,
                 int M, int K, int C, int offStride,
                 int Tin, int Tout, int actMode)
{
    extern __shared__ __align__(16) char dynsmem[];
    typedef uint2 AsT[KPA][TBM + PADA];
    typedef float BsT[TBK][TBN + PADB];
    AsT* As = reinterpret_cast<AsT*>(dynsmem);                    // As[2][16][132]
    BsT* Bs = reinterpret_cast<BsT*>(dynsmem + A_TILE_BYTES);     // Bs[2][32][132]

    const int b     = blockIdx.z;
    const int m0    = blockIdx.y * TBM;
    const int tbase = blockIdx.x * TBN;
    const int tid   = threadIdx.x;

    const int lane  = tid & 31;
    const int warp  = tid >> 5;
    const int g     = lane >> 2;
    const int tg    = lane & 3;
    const int wm    = (warp & 1) * 64;
    const int wn    = (warp >> 1) * 32;

    const float* Xb = X + (size_t)b * Tin;
    const int K2 = K >> 1;

    float acc[4][4][4];
#pragma unroll
    for (int mi = 0; mi < 4; mi++)
#pragma unroll
        for (int ni = 0; ni < 4; ni++)
#pragma unroll
            for (int r = 0; r < 4; r++) acc[mi][ni][r] = 0.f;

    // producer mapping
    const int aKp = tid >> 4;            // 0..15 k-pair row (A)
    const int aM0 = (tid & 15) * 8;      // uint2 col (A), 8 uint2 = 4x cp16
    const int bRow  = tid >> 3;          // 0..31 k row (B)
    const int bCol0 = (tid & 7) * 16;    // 16 floats per thread (B)

    const int nT = (K + TBK - 1) / TBK;

#define PREFETCH(K0, BUF)                                                          \
    {                                                                              \
        int kp = (K0) / 2 + aKp;                                                   \
        const uint2* asrc = Wp + (size_t)kp * M + m0 + aM0;                        \
        int av = (kp < K2) ? (M - (m0 + aM0)) : 0;                                 \
        _Pragma("unroll")                                                          \
        for (int i = 0; i < 4; i++) {                                              \
            int s = min(max(av - 2 * i, 0), 2) * 8;                                \
            cp16(smem_u32(&As[BUF][aKp][aM0 + 2 * i]), asrc + 2 * i, s);           \
        }                                                                          \
        int kB = (K0) + bRow;                                                      \
        bool kv = (kB < K);                                                        \
        int f = 0, off = 0;                                                        \
        if (kv) { f = kB / C; off = (kB - f * C) * offStride; }                    \
        const float* bsrc = Xb + (size_t)f * (B_ * (size_t)Tin) + off + tbase + bCol0; \
        _Pragma("unroll")                                                          \
        for (int j = 0; j < 16; j++) {                                             \
            int t = tbase + bCol0 + j;                                             \
            cp4(smem_u32(&Bs[BUF][bRow][bCol0 + j]), bsrc + j,                     \
                (kv && t < Tout) ? 4 : 0);                                         \
        }                                                                          \
        asm volatile("cp.async.commit_group;");                                    \
    }

    PREFETCH(0, 0);
    asm volatile("cp.async.wait_group 0;");
    __syncthreads();

    for (int it = 0; it < nT; it++) {
        const int buf = it & 1;
        if (it + 1 < nT) PREFETCH((it + 1) * TBK, buf ^ 1);

#pragma unroll
        for (int h = 0; h < 2; h++) {
            unsigned afh[4][4], afl[4][4], bfh[4][2], bfl[4][2];
#pragma unroll
            for (int mi = 0; mi < 4; mi++) {
                int m = wm + mi * 16 + g;
                uint2 q0 = As[buf][8 * h + tg    ][m    ];
                uint2 q1 = As[buf][8 * h + tg    ][m + 8];
                uint2 q2 = As[buf][8 * h + tg + 4][m    ];
                uint2 q3 = As[buf][8 * h + tg + 4][m + 8];
                afh[mi][0] = q0.x; afl[mi][0] = q0.y;
                afh[mi][1] = q1.x; afl[mi][1] = q1.y;
                afh[mi][2] = q2.x; afl[mi][2] = q2.y;
                afh[mi][3] = q3.x; afl[mi][3] = q3.y;
            }
#pragma unroll
            for (int ni = 0; ni < 4; ni++) {
                int n = wn + ni * 8 + g;
                pack_split_bf16(Bs[buf][16 * h + 2 * tg    ][n],
                                Bs[buf][16 * h + 2 * tg + 1][n],
                                bfh[ni][0], bfl[ni][0]);
                pack_split_bf16(Bs[buf][16 * h + 2 * tg + 8][n],
                                Bs[buf][16 * h + 2 * tg + 9][n],
                                bfh[ni][1], bfl[ni][1]);
            }
            // pass-major: 16 independent mma per pass
#pragma unroll
            for (int mi = 0; mi < 4; mi++)
#pragma unroll
                for (int ni = 0; ni < 4; ni++)
                    mma_bf16(acc[mi][ni], afh[mi][0], afh[mi][1], afh[mi][2], afh[mi][3],
                             bfh[ni][0], bfh[ni][1]);
#pragma unroll
            for (int mi = 0; mi < 4; mi++)
#pragma unroll
                for (int ni = 0; ni < 4; ni++)
                    mma_bf16(acc[mi][ni], afh[mi][0], afh[mi][1], afh[mi][2], afh[mi][3],
                             bfl[ni][0], bfl[ni][1]);
#pragma unroll
            for (int mi = 0; mi < 4; mi++)
#pragma unroll
                for (int ni = 0; ni < 4; ni++)
                    mma_bf16(acc[mi][ni], afl[mi][0], afl[mi][1], afl[mi][2], afl[mi][3],
                             bfh[ni][0], bfh[ni][1]);
        }

        if (it + 1 < nT) asm volatile("cp.async.wait_group 0;");
        __syncthreads();
    }

    // ---- epilogue: bias + activation, write [M][B][Tout] ----
    const size_t strideY = (size_t)B_ * Tout;
#pragma unroll
    for (int mi = 0; mi < 4; mi++) {
        int mA = m0 + wm + mi * 16 + g;
        int mB = mA + 8;
        float biA = (mA < M) ? bias[mA] : 0.f;
        float biB = (mB < M) ? bias[mB] : 0.f;
#pragma unroll
        for (int ni = 0; ni < 4; ni++) {
            int t = tbase + wn + ni * 8 + tg * 2;
            if (t >= Tout) continue;
            if (mA < M) {
                float2 v;
                v.x = fmaxf(acc[mi][ni][0] + biA, 0.f);
                v.y = fmaxf(acc[mi][ni][1] + biA, 0.f);
                if (actMode) { v.x = fminf(v.x, 6.f); v.y = fminf(v.y, 6.f); }
                *(float2*)&Y[(size_t)mA * strideY + (size_t)b * Tout + t] = v;
            }
            if (mB < M) {
                float2 v;
                v.x = fmaxf(acc[mi][ni][2] + biB, 0.f);
                v.y = fmaxf(acc[mi][ni][3] + biB, 0.f);
                if (actMode) { v.x = fminf(v.x, 6.f); v.y = fminf(v.y, 6.f); }
                *(float2*)&Y[(size_t)mB * strideY + (size_t)b * Tout + t] = v;
            }
        }
    }
#undef PREFETCH
}

// ---------------- per-channel batch-norm stats (over B*T) -------------------
__global__ void channel_stats(const float* __restrict__ Y, int N,
                              const float* __restrict__ gam, const float* __restrict__ bet,
                              float* __restrict__ scl, float* __restrict__ shf)
{
    int c = blockIdx.x;
    const float4* p = (const float4*)(Y + (size_t)c * N);
    int n4 = N >> 2;
    float s1 = 0.f, s2 = 0.f;
    for (int i = threadIdx.x; i < n4; i += blockDim.x) {
        float4 v = p[i];
        s1 += v.x + v.y + v.z + v.w;
        s2 += v.x*v.x + v.y*v.y + v.z*v.z + v.w*v.w;
    }
    __shared__ float r1[256], r2[256];
    r1[threadIdx.x] = s1; r2[threadIdx.x] = s2;
    __syncthreads();
    for (int s = 128; s > 0; s >>= 1) {
        if (threadIdx.x < s) {
            r1[threadIdx.x] += r1[threadIdx.x + s];
            r2[threadIdx.x] += r2[threadIdx.x + s];
        }
        __syncthreads();
    }
    if (threadIdx.x == 0) {
        float m   = r1[0] / (float)N;
        float var = r2[0] / (float)N - m * m;
        float inv = rsqrtf(var + 1e-5f);
        float g   = gam ? gam[c] : 1.f;
        float be  = bet ? bet[c] : 0.f;
        float A   = g * inv;
        scl[c] = A;
        shf[c] = be - m * A;
    }
}

// ---------------- fused bn5 stats + pooled mean/std --------------------------
__global__ void stats_pool(const float* __restrict__ A,
                           const float* __restrict__ gam, const float* __restrict__ bet,
                           float* __restrict__ P)
{
    int c   = blockIdx.x;
    int tid = threadIdx.x;
    int bb  = tid >> 3;
    int sub = tid & 7;
    const float* p = A + ((size_t)c * B_ + bb) * T3_;
    float s1 = 0.f, s2 = 0.f;
    const int n2 = T3_ >> 1;
    for (int i = sub; i < n2; i += 8) {
        float2 v = *(const float2*)(p + 2 * i);
        s1 += v.x + v.y;
        s2 += v.x * v.x + v.y * v.y;
    }
    __shared__ float r1[256], r2[256];
    r1[tid] = s1; r2[tid] = s2;
    __syncthreads();
    if (sub < 4) { r1[tid] += r1[tid + 4]; r2[tid] += r2[tid + 4]; }
    __syncthreads();
    if (sub < 2) { r1[tid] += r1[tid + 2]; r2[tid] += r2[tid + 2]; }
    __syncthreads();
    if (sub == 0) { r1[tid] += r1[tid + 1]; r2[tid] += r2[tid + 1]; }
    __syncthreads();
    __shared__ float shA, shD;
    if (tid == 0) {
        float t1 = 0.f, t2 = 0.f;
        for (int i = 0; i < 32; i++) { t1 += r1[i * 8]; t2 += r2[i * 8]; }
        float m   = t1 / (float)(B_ * T3_);
        float var = t2 / (float)(B_ * T3_) - m * m;
        float inv = rsqrtf(var + 1e-5f);
        float Aa  = gam[c] * inv;
        shA = Aa;
        shD = bet[c] - m * Aa;
    }
    __syncthreads();
    if (sub == 0) {
        float m   = r1[tid] / (float)T3_;
        float var = (r2[tid] - (float)T3_ * m * m) / (float)(T3_ - 1);
        P[bb * 3000 + c]        = shA * m + shD;
        P[bb * 3000 + 1500 + c] = fabsf(shA) * sqrtf(fmaxf(var, 0.f));
    }
}

// ---------------- dense + relu6 (one warp per output) -----------------------
__global__ void dense_relu6(const float* __restrict__ W, const float* __restrict__ bias,
                            const float* __restrict__ X, float* __restrict__ Y,
                            int M, int K)
{
    int gw   = (blockIdx.x * blockDim.x + threadIdx.x) >> 5;
    int lane = threadIdx.x & 31;
    if (gw >= B_ * M) return;
    int b = gw / M, o = gw - b * M;
    const float* w = W + (size_t)o * K;
    const float* x = X + (size_t)b * K;
    float s = 0.f;
    for (int k = lane; k < K; k += 32) s += w[k] * x[k];
#pragma unroll
    for (int off = 16; off; off >>= 1) s += __shfl_xor_sync(0xffffffffu, s, off);
    if (lane == 0) {
        float v = s + bias[o];
        Y[(size_t)b * M + o] = fminf(fmaxf(v, 0.f), 6.f);
    }
}

// ---------------- batch-norm over batch dim (B=32 == warp) ------------------
__global__ void bn_batch(const float* __restrict__ Y, const float* __restrict__ gam,
                         const float* __restrict__ bet, float* __restrict__ Out, int M)
{
    int o    = (blockIdx.x * blockDim.x + threadIdx.x) >> 5;
    int lane = threadIdx.x & 31;
    if (o >= M) return;
    float v  = Y[(size_t)lane * M + o];
    float s1 = v, s2 = v * v;
#pragma unroll
    for (int off = 16; off; off >>= 1) {
        s1 += __shfl_xor_sync(0xffffffffu, s1, off);
        s2 += __shfl_xor_sync(0xffffffffu, s2, off);
    }
    float m   = s1 * (1.f / 32.f);
    float var = s2 * (1.f / 32.f) - m * m;
    float r   = rsqrtf(var + 1e-5f);
    Out[(size_t)lane * M + o] = (v - m) * r * gam[o] + bet[o];
}

// ---------------- launch ----------------------------------------------------
extern "C" void kernel_launch(void* const* d_in, const int* in_sizes, int n_in,
                              void* d_out, int out_size)
{
    const float* x     = (const float*)d_in[0];
    const float* h1_w  = (const float*)d_in[1];
    const float* h1_b  = (const float*)d_in[2];
    const float* h2_w  = (const float*)d_in[3];
    const float* h2_b  = (const float*)d_in[4];
    const float* bn2_g = (const float*)d_in[5];
    const float* bn2_b = (const float*)d_in[6];
    const float* h3_w  = (const float*)d_in[7];
    const float* h3_b  = (const float*)d_in[8];
    const float* bn3_g = (const float*)d_in[9];
    const float* bn3_b = (const float*)d_in[10];
    const float* h4_w  = (const float*)d_in[11];
    const float* h4_b  = (const float*)d_in[12];
    const float* bn4_g = (const float*)d_in[13];
    const float* bn4_b = (const float*)d_in[14];
    const float* h5_w  = (const float*)d_in[15];
    const float* h5_b  = (const float*)d_in[16];
    const float* bn5_g = (const float*)d_in[17];
    const float* bn5_b = (const float*)d_in[18];
    const float* l1_w  = (const float*)d_in[19];
    const float* l1_b  = (const float*)d_in[20];
    const float* bn6_g = (const float*)d_in[21];
    const float* bn6_b = (const float*)d_in[22];
    const float* l2_w  = (const float*)d_in[23];
    const float* l2_b  = (const float*)d_in[24];
    const float* bn7_g = (const float*)d_in[25];
    const float* bn7_b = (const float*)d_in[26];

    float *xT, *a1, *a2, *a3, *a4, *a5, *scl, *shf, *bp, *pool, *y1, *y2;
    uint2* wp;
    cudaGetSymbolAddress((void**)&xT,   g_xT);
    cudaGetSymbolAddress((void**)&a1,   g_act1);
    cudaGetSymbolAddress((void**)&a2,   g_act2);
    cudaGetSymbolAddress((void**)&a3,   g_act3);
    cudaGetSymbolAddress((void**)&a4,   g_act4);
    cudaGetSymbolAddress((void**)&a5,   g_act5);
    cudaGetSymbolAddress((void**)&scl,  g_scl);
    cudaGetSymbolAddress((void**)&shf,  g_shf);
    cudaGetSymbolAddress((void**)&wp,   g_wp);
    cudaGetSymbolAddress((void**)&bp,   g_bp);
    cudaGetSymbolAddress((void**)&pool, g_pool);
    cudaGetSymbolAddress((void**)&y1,   g_y1);
    cudaGetSymbolAddress((void**)&y2,   g_y2);

    cudaFuncSetAttribute(gemm_splice,
                         cudaFuncAttributeMaxDynamicSharedMemorySize, SMEM_TOTAL_G);

    const int N1 = B_ * T1_;
    const int N2 = B_ * T2_;
    const int N3 = B_ * T3_;

    transpose_x<<<(B_ * T0_ * 20 + 255) / 256, 256>>>(x, xT);

    // Layer 1
    prep_wp<<<(50 * 512 + 255) / 256, 256>>>(h1_w, nullptr, wp, 512, 100, 5, 0);
    prep_bias<<<(512 + 7) / 8, 256>>>(h1_w, h1_b, nullptr, bp, 512, 100, 5, 0);
    gemm_splice<<<dim3((T1_ + 127) / 128, 4, B_), 256, SMEM_TOTAL_G>>>(
        wp, bp, xT, a1, 512, 100, 5, 1, T0_, T1_, 0);
    channel_stats<<<512, 256>>>(a1, N1, nullptr, nullptr, scl, shf);

    // Layer 2
    prep_wp<<<(768 * 512 + 255) / 256, 256>>>(h2_w, scl, wp, 512, 1536, 3, 1);
    prep_bias<<<(512 + 7) / 8, 256>>>(h2_w, h2_b, shf, bp, 512, 1536, 3, 1);
    gemm_splice<<<dim3((T2_ + 127) / 128, 4, B_), 256, SMEM_TOTAL_G>>>(
        wp, bp, a1, a2, 512, 1536, 3, 2, T1_, T2_, 0);
    channel_stats<<<512, 256>>>(a2, N2, bn2_g, bn2_b, scl, shf);

    // Layer 3
    prep_wp<<<(768 * 512 + 255) / 256, 256>>>(h3_w, scl, wp, 512, 1536, 3, 1);
    prep_bias<<<(512 + 7) / 8, 256>>>(h3_w, h3_b, shf, bp, 512, 1536, 3, 1);
    gemm_splice<<<dim3((T3_ + 127) / 128, 4, B_), 256, SMEM_TOTAL_G>>>(
        wp, bp, a2, a3, 512, 1536, 3, 3, T2_, T3_, 0);
    channel_stats<<<512, 256>>>(a3, N3, bn3_g, bn3_b, scl, shf);

    // Layer 4
    prep_wp<<<(256 * 512 + 255) / 256, 256>>>(h4_w, scl, wp, 512, 512, 1, 1);
    prep_bias<<<(512 + 7) / 8, 256>>>(h4_w, h4_b, shf, bp, 512, 512, 1, 1);
    gemm_splice<<<dim3((T3_ + 127) / 128, 4, B_), 256, SMEM_TOTAL_G>>>(
        wp, bp, a3, a4, 512, 512, 1, 0, T3_, T3_, 1);
    channel_stats<<<512, 256>>>(a4, N3, bn4_g, bn4_b, scl, shf);

    // Layer 5
    prep_wp<<<(256 * 1500 + 255) / 256, 256>>>(h5_w, scl, wp, 1500, 512, 1, 1);
    prep_bias<<<(1500 + 7) / 8, 256>>>(h5_w, h5_b, shf, bp, 1500, 512, 1, 1);
    gemm_splice<<<dim3((T3_ + 127) / 128, 12, B_), 256, SMEM_TOTAL_G>>>(
        wp, bp, a4, a5, 1500, 512, 1, 0, T3_, T3_, 1);

    stats_pool<<<1500, 256>>>(a5, bn5_g, bn5_b, pool);

    dense_relu6<<<(B_ * 512 * 32 + 255) / 256, 256>>>(l1_w, l1_b, pool, y1, 512, 3000);
    bn_batch<<<(512 * 32 + 255) / 256, 256>>>(y1, bn6_g, bn6_b, y1, 512);

    dense_relu6<<<(B_ * 512 * 32 + 255) / 256, 256>>>(l2_w, l2_b, y1, y2, 512, 512);
    bn_batch<<<(512 * 32 + 255) / 256, 256>>>(y2, bn7_g, bn7_b, (float*)d_out, 512);
}

// round 15
// speedup vs baseline: 1.2290x; 1.2290x over previous
#include <cuda_runtime.h>
#include <math.h>

#define B_  32
#define T0_ 2048
#define T1_ 2044
#define T2_ 2040
#define T3_ 2034

// ---------------- scratch (device globals; no allocations allowed) ----------
__device__ float g_xT  [20   * B_ * T0_];
__device__ float g_act1[512  * B_ * T1_];
__device__ float g_act2[512  * B_ * T2_];
__device__ float g_act3[512  * B_ * T3_];
__device__ float g_act4[512  * B_ * T3_];
__device__ float g_act5[1500 * B_ * T3_];
__device__ float g_scl [1500];
__device__ float g_shf [1500];
__device__ __align__(16) uint2 g_wp[512 * 1536 / 2];  // packed bf16 hi/lo pairs [K/2][M]
__device__ float g_bp  [1500];
__device__ float g_pool[B_ * 3000];
__device__ float g_y1  [B_ * 512];
__device__ float g_y2  [B_ * 512];

// ---------------- transpose x[b][t][f] -> xT[f][b][t] -----------------------
__global__ void transpose_x(const float* __restrict__ x, float* __restrict__ xT) {
    int idx = blockIdx.x * blockDim.x + threadIdx.x;
    const int total = B_ * T0_ * 20;
    if (idx >= total) return;
    int f = idx % 20;
    int t = (idx / 20) % T0_;
    int b = idx / (20 * T0_);
    xT[((size_t)f * B_ + b) * T0_ + t] = x[idx];
}

// ---------------- BF16 split helpers -----------------------------------------
__device__ __forceinline__ void pack_split_bf16(float v0, float v1,
                                                unsigned &hi, unsigned &lo) {
    unsigned h;
    asm("cvt.rn.bf16x2.f32 %0, %1, %2;" : "=r"(h) : "f"(v1), "f"(v0));
    float h0 = __uint_as_float(h << 16);
    float h1 = __uint_as_float(h & 0xffff0000u);
    float l0 = v0 - h0;
    float l1 = v1 - h1;
    unsigned l;
    asm("cvt.rn.bf16x2.f32 %0, %1, %2;" : "=r"(l) : "f"(l1), "f"(l0));
    hi = h; lo = l;
}

// ---------------- weight prep: transpose + fold BN scale + bf16 split --------
__global__ void prep_wp(const float* __restrict__ W, const float* __restrict__ scl,
                        uint2* __restrict__ Wp, int M, int K, int C, int hasAff)
{
    int idx = blockIdx.x * blockDim.x + threadIdx.x;
    int total = (K >> 1) * M;
    if (idx >= total) return;
    int kp = idx / M, m = idx - kp * M;
    int k0 = 2 * kp, k1 = 2 * kp + 1;
    float s0 = hasAff ? scl[k0 / C] : 1.f;
    float s1 = hasAff ? scl[k1 / C] : 1.f;
    float v0 = W[(size_t)m * K + k0] * s0;
    float v1 = W[(size_t)m * K + k1] * s1;
    unsigned h, l;
    pack_split_bf16(v0, v1, h, l);
    Wp[idx] = make_uint2(h, l);
}
__global__ void prep_bias(const float* __restrict__ W, const float* __restrict__ bias,
                          const float* __restrict__ shf, float* __restrict__ bp,
                          int M, int K, int C, int hasAff)
{
    int m    = blockIdx.x * (blockDim.x >> 5) + (threadIdx.x >> 5);
    int lane = threadIdx.x & 31;
    if (m >= M) return;
    float acc = 0.f;
    if (hasAff)
        for (int k = lane; k < K; k += 32) acc += W[(size_t)m * K + k] * shf[k / C];
#pragma unroll
    for (int off = 16; off; off >>= 1) acc += __shfl_xor_sync(0xffffffffu, acc, off);
    if (lane == 0) bp[m] = bias[m] + acc;
}

// ---------------- mma / cp.async helpers -------------------------------------
__device__ __forceinline__ void mma_bf16(float c[4],
                                         unsigned a0, unsigned a1, unsigned a2, unsigned a3,
                                         unsigned b0, unsigned b1) {
    asm("mma.sync.aligned.m16n8k16.row.col.f32.bf16.bf16.f32 "
        "{%0,%1,%2,%3}, {%4,%5,%6,%7}, {%8,%9}, {%0,%1,%2,%3};"
        : "+f"(c[0]), "+f"(c[1]), "+f"(c[2]), "+f"(c[3])
        : "r"(a0), "r"(a1), "r"(a2), "r"(a3), "r"(b0), "r"(b1));
}
__device__ __forceinline__ unsigned smem_u32(const void* p) {
    return (unsigned)__cvta_generic_to_shared(p);
}
__device__ __forceinline__ void cp16(unsigned dst, const void* src, int sbytes) {
    asm volatile("cp.async.ca.shared.global [%0], [%1], 16, %2;"
                 :: "r"(dst), "l"(src), "r"(sbytes));
}
__device__ __forceinline__ void cp4(unsigned dst, const float* src, int sbytes) {
    asm volatile("cp.async.ca.shared.global [%0], [%1], 4, %2;"
                 :: "r"(dst), "l"(src), "r"(sbytes));
}

// ---------------- fused splice + 1x1 conv GEMM -------------------------------
// 3xBF16 split-precision tensor-core GEMM (m16n8k16, fp32 accumulate).
// Block 128x128x16, 8 warps, warp tile 64x32  (the proven R12 shape).
// A: pre-split packed bf16 hi/lo uint2 (prep_wp) via cp.async -> LDS.64 frags.
// B: raw fp32 via cp.async, split+packed at fragment load.
// MMA issued PASS-MAJOR: 16 independent mma between dependent accumulations.
#define TBM 128
#define TBN 128
#define TBK 16
#define KP  8
#define PADA 4
#define PADB 4

__global__ __launch_bounds__(256, 2)
void gemm_splice(const uint2* __restrict__ Wp, const float* __restrict__ bias,
                 const float* __restrict__ X, float* __restrict__ Y,
                 int M, int K, int C, int offStride,
                 int Tin, int Tout, int actMode)
{
    __shared__ uint2 As[2][KP][TBM + PADA];
    __shared__ float Bs[2][TBK][TBN + PADB];

    const int b     = blockIdx.z;
    const int m0    = blockIdx.y * TBM;
    const int tbase = blockIdx.x * TBN;
    const int tid   = threadIdx.x;

    const int lane  = tid & 31;
    const int warp  = tid >> 5;
    const int g     = lane >> 2;
    const int tg    = lane & 3;
    const int wm    = (warp & 1) * 64;
    const int wn    = (warp >> 1) * 32;

    const float* Xb = X + (size_t)b * Tin;
    const int K2 = K >> 1;

    float acc[4][4][4];
#pragma unroll
    for (int mi = 0; mi < 4; mi++)
#pragma unroll
        for (int ni = 0; ni < 4; ni++)
#pragma unroll
            for (int r = 0; r < 4; r++) acc[mi][ni][r] = 0.f;

    // producer mapping
    const int aKp = tid >> 5;            // 0..7 k-pair row
    const int aM0 = (tid & 31) * 4;      // uint2 col
    const int bRow  = tid >> 4;          // 0..15
    const int bCol0 = (tid & 15) * 8;

    const int nT = (K + TBK - 1) / TBK;

#define PREFETCH(K0, BUF)                                                          \
    {                                                                              \
        int kp = (K0) / 2 + aKp;                                                   \
        const uint2* asrc = Wp + (size_t)kp * M + m0 + aM0;                        \
        int av = (kp < K2) ? (M - (m0 + aM0)) : 0;                                 \
        int s0 = min(max(av, 0), 2) * 8;                                           \
        int s1 = min(max(av - 2, 0), 2) * 8;                                       \
        cp16(smem_u32(&As[BUF][aKp][aM0]),     asrc,     s0);                      \
        cp16(smem_u32(&As[BUF][aKp][aM0 + 2]), asrc + 2, s1);                      \
        int kB = (K0) + bRow;                                                      \
        bool kv = (kB < K);                                                        \
        int f = 0, off = 0;                                                        \
        if (kv) { f = kB / C; off = (kB - f * C) * offStride; }                    \
        const float* bsrc = Xb + (size_t)f * (B_ * (size_t)Tin) + off + tbase + bCol0; \
        _Pragma("unroll")                                                          \
        for (int j = 0; j < 8; j++) {                                              \
            int t = tbase + bCol0 + j;                                             \
            cp4(smem_u32(&Bs[BUF][bRow][bCol0 + j]), bsrc + j,                     \
                (kv && t < Tout) ? 4 : 0);                                         \
        }                                                                          \
        asm volatile("cp.async.commit_group;");                                    \
    }

    PREFETCH(0, 0);
    asm volatile("cp.async.wait_group 0;");
    __syncthreads();

    for (int it = 0; it < nT; it++) {
        const int buf = it & 1;
        if (it + 1 < nT) PREFETCH((it + 1) * TBK, buf ^ 1);

        unsigned afh[4][4], afl[4][4], bfh[4][2], bfl[4][2];
#pragma unroll
        for (int mi = 0; mi < 4; mi++) {
            int m = wm + mi * 16 + g;
            uint2 q0 = As[buf][tg    ][m    ];
            uint2 q1 = As[buf][tg    ][m + 8];
            uint2 q2 = As[buf][tg + 4][m    ];
            uint2 q3 = As[buf][tg + 4][m + 8];
            afh[mi][0] = q0.x; afl[mi][0] = q0.y;
            afh[mi][1] = q1.x; afl[mi][1] = q1.y;
            afh[mi][2] = q2.x; afl[mi][2] = q2.y;
            afh[mi][3] = q3.x; afl[mi][3] = q3.y;
        }
#pragma unroll
        for (int ni = 0; ni < 4; ni++) {
            int n = wn + ni * 8 + g;
            pack_split_bf16(Bs[buf][2*tg    ][n], Bs[buf][2*tg + 1][n],
                            bfh[ni][0], bfl[ni][0]);
            pack_split_bf16(Bs[buf][2*tg + 8][n], Bs[buf][2*tg + 9][n],
                            bfh[ni][1], bfl[ni][1]);
        }
        // ---- pass-major: 16 independent mmas between dependent pairs ----
#pragma unroll
        for (int mi = 0; mi < 4; mi++)
#pragma unroll
            for (int ni = 0; ni < 4; ni++)
                mma_bf16(acc[mi][ni], afh[mi][0], afh[mi][1], afh[mi][2], afh[mi][3],
                         bfh[ni][0], bfh[ni][1]);
#pragma unroll
        for (int mi = 0; mi < 4; mi++)
#pragma unroll
            for (int ni = 0; ni < 4; ni++)
                mma_bf16(acc[mi][ni], afh[mi][0], afh[mi][1], afh[mi][2], afh[mi][3],
                         bfl[ni][0], bfl[ni][1]);
#pragma unroll
        for (int mi = 0; mi < 4; mi++)
#pragma unroll
            for (int ni = 0; ni < 4; ni++)
                mma_bf16(acc[mi][ni], afl[mi][0], afl[mi][1], afl[mi][2], afl[mi][3],
                         bfh[ni][0], bfh[ni][1]);

        if (it + 1 < nT) asm volatile("cp.async.wait_group 0;");
        __syncthreads();
    }

    // ---- epilogue: bias + activation, write [M][B][Tout] ----
    const size_t strideY = (size_t)B_ * Tout;
#pragma unroll
    for (int mi = 0; mi < 4; mi++) {
        int mA = m0 + wm + mi * 16 + g;
        int mB = mA + 8;
        float biA = (mA < M) ? bias[mA] : 0.f;
        float biB = (mB < M) ? bias[mB] : 0.f;
#pragma unroll
        for (int ni = 0; ni < 4; ni++) {
            int t = tbase + wn + ni * 8 + tg * 2;
            if (t >= Tout) continue;
            if (mA < M) {
                float2 v;
                v.x = fmaxf(acc[mi][ni][0] + biA, 0.f);
                v.y = fmaxf(acc[mi][ni][1] + biA, 0.f);
                if (actMode) { v.x = fminf(v.x, 6.f); v.y = fminf(v.y, 6.f); }
                *(float2*)&Y[(size_t)mA * strideY + (size_t)b * Tout + t] = v;
            }
            if (mB < M) {
                float2 v;
                v.x = fmaxf(acc[mi][ni][2] + biB, 0.f);
                v.y = fmaxf(acc[mi][ni][3] + biB, 0.f);
                if (actMode) { v.x = fminf(v.x, 6.f); v.y = fminf(v.y, 6.f); }
                *(float2*)&Y[(size_t)mB * strideY + (size_t)b * Tout + t] = v;
            }
        }
    }
#undef PREFETCH
}

// ---------------- per-channel batch-norm stats (over B*T) -------------------
__global__ void channel_stats(const float* __restrict__ Y, int N,
                              const float* __restrict__ gam, const float* __restrict__ bet,
                              float* __restrict__ scl, float* __restrict__ shf)
{
    int c = blockIdx.x;
    const float4* p = (const float4*)(Y + (size_t)c * N);
    int n4 = N >> 2;
    float s1 = 0.f, s2 = 0.f;
    for (int i = threadIdx.x; i < n4; i += blockDim.x) {
        float4 v = p[i];
        s1 += v.x + v.y + v.z + v.w;
        s2 += v.x*v.x + v.y*v.y + v.z*v.z + v.w*v.w;
    }
    __shared__ float r1[256], r2[256];
    r1[threadIdx.x] = s1; r2[threadIdx.x] = s2;
    __syncthreads();
    for (int s = 128; s > 0; s >>= 1) {
        if (threadIdx.x < s) {
            r1[threadIdx.x] += r1[threadIdx.x + s];
            r2[threadIdx.x] += r2[threadIdx.x + s];
        }
        __syncthreads();
    }
    if (threadIdx.x == 0) {
        float m   = r1[0] / (float)N;
        float var = r2[0] / (float)N - m * m;
        float inv = rsqrtf(var + 1e-5f);
        float g   = gam ? gam[c] : 1.f;
        float be  = bet ? bet[c] : 0.f;
        float A   = g * inv;
        scl[c] = A;
        shf[c] = be - m * A;
    }
}

// ---------------- fused bn5 stats + pooled mean/std --------------------------
__global__ void stats_pool(const float* __restrict__ A,
                           const float* __restrict__ gam, const float* __restrict__ bet,
                           float* __restrict__ P)
{
    int c   = blockIdx.x;
    int tid = threadIdx.x;
    int bb  = tid >> 3;
    int sub = tid & 7;
    const float* p = A + ((size_t)c * B_ + bb) * T3_;
    float s1 = 0.f, s2 = 0.f;
    const int n2 = T3_ >> 1;
    for (int i = sub; i < n2; i += 8) {
        float2 v = *(const float2*)(p + 2 * i);
        s1 += v.x + v.y;
        s2 += v.x * v.x + v.y * v.y;
    }
    __shared__ float r1[256], r2[256];
    r1[tid] = s1; r2[tid] = s2;
    __syncthreads();
    if (sub < 4) { r1[tid] += r1[tid + 4]; r2[tid] += r2[tid + 4]; }
    __syncthreads();
    if (sub < 2) { r1[tid] += r1[tid + 2]; r2[tid] += r2[tid + 2]; }
    __syncthreads();
    if (sub == 0) { r1[tid] += r1[tid + 1]; r2[tid] += r2[tid + 1]; }
    __syncthreads();
    __shared__ float shA, shD;
    if (tid == 0) {
        float t1 = 0.f, t2 = 0.f;
        for (int i = 0; i < 32; i++) { t1 += r1[i * 8]; t2 += r2[i * 8]; }
        float m   = t1 / (float)(B_ * T3_);
        float var = t2 / (float)(B_ * T3_) - m * m;
        float inv = rsqrtf(var + 1e-5f);
        float Aa  = gam[c] * inv;
        shA = Aa;
        shD = bet[c] - m * Aa;
    }
    __syncthreads();
    if (sub == 0) {
        float m   = r1[tid] / (float)T3_;
        float var = (r2[tid] - (float)T3_ * m * m) / (float)(T3_ - 1);
        P[bb * 3000 + c]        = shA * m + shD;
        P[bb * 3000 + 1500 + c] = fabsf(shA) * sqrtf(fmaxf(var, 0.f));
    }
}

// ---------------- dense + relu6 (one warp per output) -----------------------
__global__ void dense_relu6(const float* __restrict__ W, const float* __restrict__ bias,
                            const float* __restrict__ X, float* __restrict__ Y,
                            int M, int K)
{
    int gw   = (blockIdx.x * blockDim.x + threadIdx.x) >> 5;
    int lane = threadIdx.x & 31;
    if (gw >= B_ * M) return;
    int b = gw / M, o = gw - b * M;
    const float* w = W + (size_t)o * K;
    const float* x = X + (size_t)b * K;
    float s = 0.f;
    for (int k = lane; k < K; k += 32) s += w[k] * x[k];
#pragma unroll
    for (int off = 16; off; off >>= 1) s += __shfl_xor_sync(0xffffffffu, s, off);
    if (lane == 0) {
        float v = s + bias[o];
        Y[(size_t)b * M + o] = fminf(fmaxf(v, 0.f), 6.f);
    }
}

// ---------------- batch-norm over batch dim (B=32 == warp) ------------------
__global__ void bn_batch(const float* __restrict__ Y, const float* __restrict__ gam,
                         const float* __restrict__ bet, float* __restrict__ Out, int M)
{
    int o    = (blockIdx.x * blockDim.x + threadIdx.x) >> 5;
    int lane = threadIdx.x & 31;
    if (o >= M) return;
    float v  = Y[(size_t)lane * M + o];
    float s1 = v, s2 = v * v;
#pragma unroll
    for (int off = 16; off; off >>= 1) {
        s1 += __shfl_xor_sync(0xffffffffu, s1, off);
        s2 += __shfl_xor_sync(0xffffffffu, s2, off);
    }
    float m   = s1 * (1.f / 32.f);
    float var = s2 * (1.f / 32.f) - m * m;
    float r   = rsqrtf(var + 1e-5f);
    Out[(size_t)lane * M + o] = (v - m) * r * gam[o] + bet[o];
}

// ---------------- launch ----------------------------------------------------
extern "C" void kernel_launch(void* const* d_in, const int* in_sizes, int n_in,
                              void* d_out, int out_size)
{
    const float* x     = (const float*)d_in[0];
    const float* h1_w  = (const float*)d_in[1];
    const float* h1_b  = (const float*)d_in[2];
    const float* h2_w  = (const float*)d_in[3];
    const float* h2_b  = (const float*)d_in[4];
    const float* bn2_g = (const float*)d_in[5];
    const float* bn2_b = (const float*)d_in[6];
    const float* h3_w  = (const float*)d_in[7];
    const float* h3_b  = (const float*)d_in[8];
    const float* bn3_g = (const float*)d_in[9];
    const float* bn3_b = (const float*)d_in[10];
    const float* h4_w  = (const float*)d_in[11];
    const float* h4_b  = (const float*)d_in[12];
    const float* bn4_g = (const float*)d_in[13];
    const float* bn4_b = (const float*)d_in[14];
    const float* h5_w  = (const float*)d_in[15];
    const float* h5_b  = (const float*)d_in[16];
    const float* bn5_g = (const float*)d_in[17];
    const float* bn5_b = (const float*)d_in[18];
    const float* l1_w  = (const float*)d_in[19];
    const float* l1_b  = (const float*)d_in[20];
    const float* bn6_g = (const float*)d_in[21];
    const float* bn6_b = (const float*)d_in[22];
    const float* l2_w  = (const float*)d_in[23];
    const float* l2_b  = (const float*)d_in[24];
    const float* bn7_g = (const float*)d_in[25];
    const float* bn7_b = (const float*)d_in[26];

    float *xT, *a1, *a2, *a3, *a4, *a5, *scl, *shf, *bp, *pool, *y1, *y2;
    uint2* wp;
    cudaGetSymbolAddress((void**)&xT,   g_xT);
    cudaGetSymbolAddress((void**)&a1,   g_act1);
    cudaGetSymbolAddress((void**)&a2,   g_act2);
    cudaGetSymbolAddress((void**)&a3,   g_act3);
    cudaGetSymbolAddress((void**)&a4,   g_act4);
    cudaGetSymbolAddress((void**)&a5,   g_act5);
    cudaGetSymbolAddress((void**)&scl,  g_scl);
    cudaGetSymbolAddress((void**)&shf,  g_shf);
    cudaGetSymbolAddress((void**)&wp,   g_wp);
    cudaGetSymbolAddress((void**)&bp,   g_bp);
    cudaGetSymbolAddress((void**)&pool, g_pool);
    cudaGetSymbolAddress((void**)&y1,   g_y1);
    cudaGetSymbolAddress((void**)&y2,   g_y2);

    const int N1 = B_ * T1_;
    const int N2 = B_ * T2_;
    const int N3 = B_ * T3_;

    transpose_x<<<(B_ * T0_ * 20 + 255) / 256, 256>>>(x, xT);

    // Layer 1
    prep_wp<<<(50 * 512 + 255) / 256, 256>>>(h1_w, nullptr, wp, 512, 100, 5, 0);
    prep_bias<<<(512 + 7) / 8, 256>>>(h1_w, h1_b, nullptr, bp, 512, 100, 5, 0);
    gemm_splice<<<dim3((T1_ + 127) / 128, 4, B_), 256>>>(
        wp, bp, xT, a1, 512, 100, 5, 1, T0_, T1_, 0);
    channel_stats<<<512, 256>>>(a1, N1, nullptr, nullptr, scl, shf);

    // Layer 2
    prep_wp<<<(768 * 512 + 255) / 256, 256>>>(h2_w, scl, wp, 512, 1536, 3, 1);
    prep_bias<<<(512 + 7) / 8, 256>>>(h2_w, h2_b, shf, bp, 512, 1536, 3, 1);
    gemm_splice<<<dim3((T2_ + 127) / 128, 4, B_), 256>>>(
        wp, bp, a1, a2, 512, 1536, 3, 2, T1_, T2_, 0);
    channel_stats<<<512, 256>>>(a2, N2, bn2_g, bn2_b, scl, shf);

    // Layer 3
    prep_wp<<<(768 * 512 + 255) / 256, 256>>>(h3_w, scl, wp, 512, 1536, 3, 1);
    prep_bias<<<(512 + 7) / 8, 256>>>(h3_w, h3_b, shf, bp, 512, 1536, 3, 1);
    gemm_splice<<<dim3((T3_ + 127) / 128, 4, B_), 256>>>(
        wp, bp, a2, a3, 512, 1536, 3, 3, T2_, T3_, 0);
    channel_stats<<<512, 256>>>(a3, N3, bn3_g, bn3_b, scl, shf);

    // Layer 4
    prep_wp<<<(256 * 512 + 255) / 256, 256>>>(h4_w, scl, wp, 512, 512, 1, 1);
    prep_bias<<<(512 + 7) / 8, 256>>>(h4_w, h4_b, shf, bp, 512, 512, 1, 1);
    gemm_splice<<<dim3((T3_ + 127) / 128, 4, B_), 256>>>(
        wp, bp, a3, a4, 512, 512, 1, 0, T3_, T3_, 1);
    channel_stats<<<512, 256>>>(a4, N3, bn4_g, bn4_b, scl, shf);

    // Layer 5
    prep_wp<<<(256 * 1500 + 255) / 256, 256>>>(h5_w, scl, wp, 1500, 512, 1, 1);
    prep_bias<<<(1500 + 7) / 8, 256>>>(h5_w, h5_b, shf, bp, 1500, 512, 1, 1);
    gemm_splice<<<dim3((T3_ + 127) / 128, 12, B_), 256>>>(
        wp, bp, a4, a5, 1500, 512, 1, 0, T3_, T3_, 1);

    stats_pool<<<1500, 256>>>(a5, bn5_g, bn5_b, pool);

    dense_relu6<<<(B_ * 512 * 32 + 255) / 256, 256>>>(l1_w, l1_b, pool, y1, 512, 3000);
    bn_batch<<<(512 * 32 + 255) / 256, 256>>>(y1, bn6_g, bn6_b, y1, 512);

    dense_relu6<<<(B_ * 512 * 32 + 255) / 256, 256>>>(l2_w, l2_b, y1, y2, 512, 512);
    bn_batch<<<(512 * 32 + 255) / 256, 256>>>(y2, bn7_g, bn7_b, (float*)d_out, 512);
}

// round 16
// speedup vs baseline: 1.4253x; 1.1597x over previous
#include <cuda_runtime.h>
#include <math.h>

#define B_  32
#define T0_ 2048
#define T1_ 2044
#define T2_ 2040
#define T3_ 2034
#define T3P 2036   // padded stride for a3/a4 (16B-aligned rows)

// ---------------- scratch (device globals; no allocations allowed) ----------
__device__ float g_xT  [20   * B_ * T0_];
__device__ float g_act1[512  * B_ * T1_];
__device__ float g_act2[512  * B_ * T2_];
__device__ float g_act3[512  * B_ * T3P];
__device__ float g_act4[512  * B_ * T3P];
__device__ float g_act5[1500 * B_ * T3_];
__device__ float g_scl [1500];
__device__ float g_shf [1500];
__device__ __align__(16) uint2 g_wp[512 * 1536 / 2];  // packed bf16 hi/lo pairs [K/2][M]
__device__ float g_bp  [1500];
__device__ float g_pool[B_ * 3000];
__device__ float g_y1  [B_ * 512];
__device__ float g_y2  [B_ * 512];

// ---------------- transpose x[b][t][f] -> xT[f][b][t] -----------------------
__global__ void transpose_x(const float* __restrict__ x, float* __restrict__ xT) {
    int idx = blockIdx.x * blockDim.x + threadIdx.x;
    const int total = B_ * T0_ * 20;
    if (idx >= total) return;
    int f = idx % 20;
    int t = (idx / 20) % T0_;
    int b = idx / (20 * T0_);
    xT[((size_t)f * B_ + b) * T0_ + t] = x[idx];
}

// ---------------- BF16 split helpers -----------------------------------------
__device__ __forceinline__ void pack_split_bf16(float v0, float v1,
                                                unsigned &hi, unsigned &lo) {
    unsigned h;
    asm("cvt.rn.bf16x2.f32 %0, %1, %2;" : "=r"(h) : "f"(v1), "f"(v0));
    float h0 = __uint_as_float(h << 16);
    float h1 = __uint_as_float(h & 0xffff0000u);
    float l0 = v0 - h0;
    float l1 = v1 - h1;
    unsigned l;
    asm("cvt.rn.bf16x2.f32 %0, %1, %2;" : "=r"(l) : "f"(l1), "f"(l0));
    hi = h; lo = l;
}

// ---------------- weight prep: transpose + fold BN scale + bf16 split --------
__global__ void prep_wp(const float* __restrict__ W, const float* __restrict__ scl,
                        uint2* __restrict__ Wp, int M, int K, int C, int hasAff)
{
    int idx = blockIdx.x * blockDim.x + threadIdx.x;
    int total = (K >> 1) * M;
    if (idx >= total) return;
    int kp = idx / M, m = idx - kp * M;
    int k0 = 2 * kp, k1 = 2 * kp + 1;
    float s0 = hasAff ? scl[k0 / C] : 1.f;
    float s1 = hasAff ? scl[k1 / C] : 1.f;
    float v0 = W[(size_t)m * K + k0] * s0;
    float v1 = W[(size_t)m * K + k1] * s1;
    unsigned h, l;
    pack_split_bf16(v0, v1, h, l);
    Wp[idx] = make_uint2(h, l);
}
__global__ void prep_bias(const float* __restrict__ W, const float* __restrict__ bias,
                          const float* __restrict__ shf, float* __restrict__ bp,
                          int M, int K, int C, int hasAff)
{
    int m    = blockIdx.x * (blockDim.x >> 5) + (threadIdx.x >> 5);
    int lane = threadIdx.x & 31;
    if (m >= M) return;
    float acc = 0.f;
    if (hasAff)
        for (int k = lane; k < K; k += 32) acc += W[(size_t)m * K + k] * shf[k / C];
#pragma unroll
    for (int off = 16; off; off >>= 1) acc += __shfl_xor_sync(0xffffffffu, acc, off);
    if (lane == 0) bp[m] = bias[m] + acc;
}

// ---------------- mma / cp.async helpers -------------------------------------
__device__ __forceinline__ void mma_bf16(float c[4],
                                         unsigned a0, unsigned a1, unsigned a2, unsigned a3,
                                         unsigned b0, unsigned b1) {
    asm("mma.sync.aligned.m16n8k16.row.col.f32.bf16.bf16.f32 "
        "{%0,%1,%2,%3}, {%4,%5,%6,%7}, {%8,%9}, {%0,%1,%2,%3};"
        : "+f"(c[0]), "+f"(c[1]), "+f"(c[2]), "+f"(c[3])
        : "r"(a0), "r"(a1), "r"(a2), "r"(a3), "r"(b0), "r"(b1));
}
__device__ __forceinline__ unsigned smem_u32(const void* p) {
    return (unsigned)__cvta_generic_to_shared(p);
}
__device__ __forceinline__ void cp16(unsigned dst, const void* src, int sbytes) {
    asm volatile("cp.async.ca.shared.global [%0], [%1], 16, %2;"
                 :: "r"(dst), "l"(src), "r"(sbytes));
}

// ---------------- fused splice + 1x1 conv GEMM -------------------------------
// 3xBF16 split-precision tensor-core GEMM (m16n8k16, fp32 accumulate).
// Block 128x128x16, 8 warps, warp tile 64x32.
// A: pre-split packed bf16 hi/lo uint2 via cp.async (16B) -> LDS.64 fragments.
// B: EXTENDED SOURCE ROWS — one smem row per distinct source channel f, length
//    144 floats, copied with 16B cp.async only. k-rows are views
//    Bs[row(k)][off(k)+n]; row 16 is a zero row for k >= K (avoids 0*garbage).
// C_/OS_ are template params so k/C is a mul-shift.
#define TBM 128
#define TBN 128
#define TBK 16
#define KP  8
#define PADA 4
#define BROW 148      // row pitch (floats); 592B = 37*16 -> rows 16B aligned

template<int C_, int OS_>
__global__ __launch_bounds__(256, 2)
void gemm_splice(const uint2* __restrict__ Wp, const float* __restrict__ bias,
                 const float* __restrict__ X, float* __restrict__ Y,
                 int M, int K, int Tin, int TinP, int Tout, int ToutP, int actMode)
{
    __shared__ uint2 As[2][KP][TBM + PADA];
    __shared__ float Bs[2][17][BROW];

    const int b     = blockIdx.z;
    const int m0    = blockIdx.y * TBM;
    const int tbase = blockIdx.x * TBN;
    const int tid   = threadIdx.x;

    const int lane  = tid & 31;
    const int warp  = tid >> 5;
    const int g     = lane >> 2;
    const int tg    = lane & 3;
    const int wm    = (warp & 1) * 64;
    const int wn    = (warp >> 1) * 32;

    const int K2 = K >> 1;

    float acc[4][4][4];
#pragma unroll
    for (int mi = 0; mi < 4; mi++)
#pragma unroll
        for (int ni = 0; ni < 4; ni++)
#pragma unroll
            for (int r = 0; r < 4; r++) acc[mi][ni][r] = 0.f;

    // producer mapping
    const int aKp = tid >> 5;            // 0..7 k-pair row (A)
    const int aM0 = (tid & 31) * 4;      // uint2 col (A)
    const int bRowP = tid >> 4;          // 0..15 source-row (B)
    const int bC16  = tid & 15;          // 16B-chunk lane (B)

    const int nT = (K + TBK - 1) / TBK;
    const int availB = (Tin - tbase) * 4;   // valid bytes in any source row

    // zero row 16 of both buffers (used by k >= K)
    for (int i = tid; i < BROW; i += 256) { Bs[0][16][i] = 0.f; Bs[1][16][i] = 0.f; }

#define PREFETCH(K0, BUF)                                                          \
    {                                                                              \
        int kp = (K0) / 2 + aKp;                                                   \
        const uint2* asrc = Wp + (size_t)kp * M + m0 + aM0;                        \
        int av = (kp < K2) ? (M - (m0 + aM0)) : 0;                                 \
        int s0 = min(max(av, 0), 2) * 8;                                           \
        int s1 = min(max(av - 2, 0), 2) * 8;                                       \
        cp16(smem_u32(&As[BUF][aKp][aM0]),     asrc,     s0);                      \
        cp16(smem_u32(&As[BUF][aKp][aM0 + 2]), asrc + 2, s1);                      \
        int fLo = (K0) / C_;                                                       \
        int f = fLo + bRowP;                                                       \
        int kHi = min((K0) + TBK - 1, K - 1);                                      \
        if (f * C_ <= kHi) {                                                       \
            const char* bsrc = (const char*)(X + ((size_t)f * B_ + b) * TinP + tbase); \
            _Pragma("unroll")                                                      \
            for (int cc = 0; cc < 3; cc++) {                                       \
                int chunk = bC16 + 16 * cc;                                        \
                if (chunk < 36) {                                                  \
                    int s = min(max(availB - chunk * 16, 0), 16);                  \
                    cp16(smem_u32((char*)&Bs[BUF][bRowP][0] + chunk * 16),         \
                         bsrc + chunk * 16, s);                                    \
                }                                                                  \
            }                                                                      \
        }                                                                          \
        asm volatile("cp.async.commit_group;");                                    \
    }

    PREFETCH(0, 0);
    asm volatile("cp.async.wait_group 0;");
    __syncthreads();

    for (int it = 0; it < nT; it++) {
        const int buf = it & 1;
        const int k0  = it * TBK;
        if (it + 1 < nT) PREFETCH((it + 1) * TBK, buf ^ 1);

        // per-thread (row, off) for this tile's 4 B k-indices
        int rr[4], oo[4];
        {
            int fLo = k0 / C_;
            int ks[4] = {k0 + 2*tg, k0 + 2*tg + 1, k0 + 2*tg + 8, k0 + 2*tg + 9};
#pragma unroll
            for (int i = 0; i < 4; i++) {
                if (ks[i] < K) {
                    int f = ks[i] / C_;
                    rr[i] = f - fLo;
                    oo[i] = (ks[i] - f * C_) * OS_;
                } else { rr[i] = 16; oo[i] = 0; }
            }
        }

        unsigned afh[4][4], afl[4][4], bfh[4][2], bfl[4][2];
#pragma unroll
        for (int mi = 0; mi < 4; mi++) {
            int m = wm + mi * 16 + g;
            uint2 q0 = As[buf][tg    ][m    ];
            uint2 q1 = As[buf][tg    ][m + 8];
            uint2 q2 = As[buf][tg + 4][m    ];
            uint2 q3 = As[buf][tg + 4][m + 8];
            afh[mi][0] = q0.x; afl[mi][0] = q0.y;
            afh[mi][1] = q1.x; afl[mi][1] = q1.y;
            afh[mi][2] = q2.x; afl[mi][2] = q2.y;
            afh[mi][3] = q3.x; afl[mi][3] = q3.y;
        }
#pragma unroll
        for (int ni = 0; ni < 4; ni++) {
            int n = wn + ni * 8 + g;
            pack_split_bf16(Bs[buf][rr[0]][oo[0] + n], Bs[buf][rr[1]][oo[1] + n],
                            bfh[ni][0], bfl[ni][0]);
            pack_split_bf16(Bs[buf][rr[2]][oo[2] + n], Bs[buf][rr[3]][oo[3] + n],
                            bfh[ni][1], bfl[ni][1]);
        }
#pragma unroll
        for (int mi = 0; mi < 4; mi++)
#pragma unroll
            for (int ni = 0; ni < 4; ni++) {
                mma_bf16(acc[mi][ni], afh[mi][0], afh[mi][1], afh[mi][2], afh[mi][3],
                         bfh[ni][0], bfh[ni][1]);
                mma_bf16(acc[mi][ni], afh[mi][0], afh[mi][1], afh[mi][2], afh[mi][3],
                         bfl[ni][0], bfl[ni][1]);
                mma_bf16(acc[mi][ni], afl[mi][0], afl[mi][1], afl[mi][2], afl[mi][3],
                         bfh[ni][0], bfh[ni][1]);
            }

        if (it + 1 < nT) asm volatile("cp.async.wait_group 0;");
        __syncthreads();
    }

    // ---- epilogue: bias + activation, write [M][B][ToutP] ----
#pragma unroll
    for (int mi = 0; mi < 4; mi++) {
        int mA = m0 + wm + mi * 16 + g;
        int mB = mA + 8;
        float biA = (mA < M) ? bias[mA] : 0.f;
        float biB = (mB < M) ? bias[mB] : 0.f;
#pragma unroll
        for (int ni = 0; ni < 4; ni++) {
            int t = tbase + wn + ni * 8 + tg * 2;
            if (t >= Tout) continue;
            if (mA < M) {
                float2 v;
                v.x = fmaxf(acc[mi][ni][0] + biA, 0.f);
                v.y = fmaxf(acc[mi][ni][1] + biA, 0.f);
                if (actMode) { v.x = fminf(v.x, 6.f); v.y = fminf(v.y, 6.f); }
                *(float2*)&Y[((size_t)mA * B_ + b) * ToutP + t] = v;
            }
            if (mB < M) {
                float2 v;
                v.x = fmaxf(acc[mi][ni][2] + biB, 0.f);
                v.y = fmaxf(acc[mi][ni][3] + biB, 0.f);
                if (actMode) { v.x = fminf(v.x, 6.f); v.y = fminf(v.y, 6.f); }
                *(float2*)&Y[((size_t)mB * B_ + b) * ToutP + t] = v;
            }
        }
    }
#undef PREFETCH
}

// ---------------- per-channel batch-norm stats (over B*T, padded stride) -----
__global__ void channel_stats(const float* __restrict__ Y, int T, int TP,
                              const float* __restrict__ gam, const float* __restrict__ bet,
                              float* __restrict__ scl, float* __restrict__ shf)
{
    int c = blockIdx.x;
    float s1 = 0.f, s2 = 0.f;
    int n2 = T >> 1;
    for (int bb = 0; bb < B_; bb++) {
        const float2* p = (const float2*)(Y + ((size_t)c * B_ + bb) * TP);
        for (int i = threadIdx.x; i < n2; i += blockDim.x) {
            float2 v = p[i];
            s1 += v.x + v.y;
            s2 += v.x * v.x + v.y * v.y;
        }
    }
    __shared__ float r1[256], r2[256];
    r1[threadIdx.x] = s1; r2[threadIdx.x] = s2;
    __syncthreads();
    for (int s = 128; s > 0; s >>= 1) {
        if (threadIdx.x < s) {
            r1[threadIdx.x] += r1[threadIdx.x + s];
            r2[threadIdx.x] += r2[threadIdx.x + s];
        }
        __syncthreads();
    }
    if (threadIdx.x == 0) {
        float N   = (float)(B_ * T);
        float m   = r1[0] / N;
        float var = r2[0] / N - m * m;
        float inv = rsqrtf(var + 1e-5f);
        float g   = gam ? gam[c] : 1.f;
        float be  = bet ? bet[c] : 0.f;
        float A   = g * inv;
        scl[c] = A;
        shf[c] = be - m * A;
    }
}

// ---------------- fused bn5 stats + pooled mean/std --------------------------
__global__ void stats_pool(const float* __restrict__ A,
                           const float* __restrict__ gam, const float* __restrict__ bet,
                           float* __restrict__ P)
{
    int c   = blockIdx.x;
    int tid = threadIdx.x;
    int bb  = tid >> 3;
    int sub = tid & 7;
    const float* p = A + ((size_t)c * B_ + bb) * T3_;
    float s1 = 0.f, s2 = 0.f;
    const int n2 = T3_ >> 1;
    for (int i = sub; i < n2; i += 8) {
        float2 v = *(const float2*)(p + 2 * i);
        s1 += v.x + v.y;
        s2 += v.x * v.x + v.y * v.y;
    }
    __shared__ float r1[256], r2[256];
    r1[tid] = s1; r2[tid] = s2;
    __syncthreads();
    if (sub < 4) { r1[tid] += r1[tid + 4]; r2[tid] += r2[tid + 4]; }
    __syncthreads();
    if (sub < 2) { r1[tid] += r1[tid + 2]; r2[tid] += r2[tid + 2]; }
    __syncthreads();
    if (sub == 0) { r1[tid] += r1[tid + 1]; r2[tid] += r2[tid + 1]; }
    __syncthreads();
    __shared__ float shA, shD;
    if (tid == 0) {
        float t1 = 0.f, t2 = 0.f;
        for (int i = 0; i < 32; i++) { t1 += r1[i * 8]; t2 += r2[i * 8]; }
        float m   = t1 / (float)(B_ * T3_);
        float var = t2 / (float)(B_ * T3_) - m * m;
        float inv = rsqrtf(var + 1e-5f);
        float Aa  = gam[c] * inv;
        shA = Aa;
        shD = bet[c] - m * Aa;
    }
    __syncthreads();
    if (sub == 0) {
        float m   = r1[tid] / (float)T3_;
        float var = (r2[tid] - (float)T3_ * m * m) / (float)(T3_ - 1);
        P[bb * 3000 + c]        = shA * m + shD;
        P[bb * 3000 + 1500 + c] = fabsf(shA) * sqrtf(fmaxf(var, 0.f));
    }
}

// ---------------- dense + relu6 (one warp per output) -----------------------
__global__ void dense_relu6(const float* __restrict__ W, const float* __restrict__ bias,
                            const float* __restrict__ X, float* __restrict__ Y,
                            int M, int K)
{
    int gw   = (blockIdx.x * blockDim.x + threadIdx.x) >> 5;
    int lane = threadIdx.x & 31;
    if (gw >= B_ * M) return;
    int b = gw / M, o = gw - b * M;
    const float* w = W + (size_t)o * K;
    const float* x = X + (size_t)b * K;
    float s = 0.f;
    for (int k = lane; k < K; k += 32) s += w[k] * x[k];
#pragma unroll
    for (int off = 16; off; off >>= 1) s += __shfl_xor_sync(0xffffffffu, s, off);
    if (lane == 0) {
        float v = s + bias[o];
        Y[(size_t)b * M + o] = fminf(fmaxf(v, 0.f), 6.f);
    }
}

// ---------------- batch-norm over batch dim (B=32 == warp) ------------------
__global__ void bn_batch(const float* __restrict__ Y, const float* __restrict__ gam,
                         const float* __restrict__ bet, float* __restrict__ Out, int M)
{
    int o    = (blockIdx.x * blockDim.x + threadIdx.x) >> 5;
    int lane = threadIdx.x & 31;
    if (o >= M) return;
    float v  = Y[(size_t)lane * M + o];
    float s1 = v, s2 = v * v;
#pragma unroll
    for (int off = 16; off; off >>= 1) {
        s1 += __shfl_xor_sync(0xffffffffu, s1, off);
        s2 += __shfl_xor_sync(0xffffffffu, s2, off);
    }
    float m   = s1 * (1.f / 32.f);
    float var = s2 * (1.f / 32.f) - m * m;
    float r   = rsqrtf(var + 1e-5f);
    Out[(size_t)lane * M + o] = (v - m) * r * gam[o] + bet[o];
}

// ---------------- launch ----------------------------------------------------
extern "C" void kernel_launch(void* const* d_in, const int* in_sizes, int n_in,
                              void* d_out, int out_size)
{
    const float* x     = (const float*)d_in[0];
    const float* h1_w  = (const float*)d_in[1];
    const float* h1_b  = (const float*)d_in[2];
    const float* h2_w  = (const float*)d_in[3];
    const float* h2_b  = (const float*)d_in[4];
    const float* bn2_g = (const float*)d_in[5];
    const float* bn2_b = (const float*)d_in[6];
    const float* h3_w  = (const float*)d_in[7];
    const float* h3_b  = (const float*)d_in[8];
    const float* bn3_g = (const float*)d_in[9];
    const float* bn3_b = (const float*)d_in[10];
    const float* h4_w  = (const float*)d_in[11];
    const float* h4_b  = (const float*)d_in[12];
    const float* bn4_g = (const float*)d_in[13];
    const float* bn4_b = (const float*)d_in[14];
    const float* h5_w  = (const float*)d_in[15];
    const float* h5_b  = (const float*)d_in[16];
    const float* bn5_g = (const float*)d_in[17];
    const float* bn5_b = (const float*)d_in[18];
    const float* l1_w  = (const float*)d_in[19];
    const float* l1_b  = (const float*)d_in[20];
    const float* bn6_g = (const float*)d_in[21];
    const float* bn6_b = (const float*)d_in[22];
    const float* l2_w  = (const float*)d_in[23];
    const float* l2_b  = (const float*)d_in[24];
    const float* bn7_g = (const float*)d_in[25];
    const float* bn7_b = (const float*)d_in[26];

    float *xT, *a1, *a2, *a3, *a4, *a5, *scl, *shf, *bp, *pool, *y1, *y2;
    uint2* wp;
    cudaGetSymbolAddress((void**)&xT,   g_xT);
    cudaGetSymbolAddress((void**)&a1,   g_act1);
    cudaGetSymbolAddress((void**)&a2,   g_act2);
    cudaGetSymbolAddress((void**)&a3,   g_act3);
    cudaGetSymbolAddress((void**)&a4,   g_act4);
    cudaGetSymbolAddress((void**)&a5,   g_act5);
    cudaGetSymbolAddress((void**)&scl,  g_scl);
    cudaGetSymbolAddress((void**)&shf,  g_shf);
    cudaGetSymbolAddress((void**)&wp,   g_wp);
    cudaGetSymbolAddress((void**)&bp,   g_bp);
    cudaGetSymbolAddress((void**)&pool, g_pool);
    cudaGetSymbolAddress((void**)&y1,   g_y1);
    cudaGetSymbolAddress((void**)&y2,   g_y2);

    transpose_x<<<(B_ * T0_ * 20 + 255) / 256, 256>>>(x, xT);

    // Layer 1: splice(0..4), C=5, OS=1
    prep_wp<<<(50 * 512 + 255) / 256, 256>>>(h1_w, nullptr, wp, 512, 100, 5, 0);
    prep_bias<<<(512 + 7) / 8, 256>>>(h1_w, h1_b, nullptr, bp, 512, 100, 5, 0);
    gemm_splice<5, 1><<<dim3((T1_ + 127) / 128, 4, B_), 256>>>(
        wp, bp, xT, a1, 512, 100, T0_, T0_, T1_, T1_, 0);
    channel_stats<<<512, 256>>>(a1, T1_, T1_, nullptr, nullptr, scl, shf);

    // Layer 2: splice(0,2,4), C=3, OS=2
    prep_wp<<<(768 * 512 + 255) / 256, 256>>>(h2_w, scl, wp, 512, 1536, 3, 1);
    prep_bias<<<(512 + 7) / 8, 256>>>(h2_w, h2_b, shf, bp, 512, 1536, 3, 1);
    gemm_splice<3, 2><<<dim3((T2_ + 127) / 128, 4, B_), 256>>>(
        wp, bp, a1, a2, 512, 1536, T1_, T1_, T2_, T2_, 0);
    channel_stats<<<512, 256>>>(a2, T2_, T2_, bn2_g, bn2_b, scl, shf);

    // Layer 3: splice(0,3,6), C=3, OS=3  (output padded stride T3P)
    prep_wp<<<(768 * 512 + 255) / 256, 256>>>(h3_w, scl, wp, 512, 1536, 3, 1);
    prep_bias<<<(512 + 7) / 8, 256>>>(h3_w, h3_b, shf, bp, 512, 1536, 3, 1);
    gemm_splice<3, 3><<<dim3((T3_ + 127) / 128, 4, B_), 256>>>(
        wp, bp, a2, a3, 512, 1536, T2_, T2_, T3_, T3P, 0);
    channel_stats<<<512, 256>>>(a3, T3_, T3P, bn3_g, bn3_b, scl, shf);

    // Layer 4: C=1, OS=0
    prep_wp<<<(256 * 512 + 255) / 256, 256>>>(h4_w, scl, wp, 512, 512, 1, 1);
    prep_bias<<<(512 + 7) / 8, 256>>>(h4_w, h4_b, shf, bp, 512, 512, 1, 1);
    gemm_splice<1, 0><<<dim3((T3_ + 127) / 128, 4, B_), 256>>>(
        wp, bp, a3, a4, 512, 512, T3_, T3P, T3_, T3P, 1);
    channel_stats<<<512, 256>>>(a4, T3_, T3P, bn4_g, bn4_b, scl, shf);

    // Layer 5: C=1, OS=0  (output tight stride: only stats_pool reads it)
    prep_wp<<<(256 * 1500 + 255) / 256, 256>>>(h5_w, scl, wp, 1500, 512, 1, 1);
    prep_bias<<<(1500 + 7) / 8, 256>>>(h5_w, h5_b, shf, bp, 1500, 512, 1, 1);
    gemm_splice<1, 0><<<dim3((T3_ + 127) / 128, 12, B_), 256>>>(
        wp, bp, a4, a5, 1500, 512, T3_, T3P, T3_, T3_, 1);

    stats_pool<<<1500, 256>>>(a5, bn5_g, bn5_b, pool);

    dense_relu6<<<(B_ * 512 * 32 + 255) / 256, 256>>>(l1_w, l1_b, pool, y1, 512, 3000);
    bn_batch<<<(512 * 32 + 255) / 256, 256>>>(y1, bn6_g, bn6_b, y1, 512);

    dense_relu6<<<(B_ * 512 * 32 + 255) / 256, 256>>>(l2_w, l2_b, y1, y2, 512, 512);
    bn_batch<<<(512 * 32 + 255) / 256, 256>>>(y2, bn7_g, bn7_b, (float*)d_out, 512);
}